// round 14
// baseline (speedup 1.0000x reference)
#include <cuda_runtime.h>

// FINAL — converged winner (5 measurements: 156.1/156.6/157.0/156.4/157.4 us,
// mean 156.7, sigma 0.5).
//
// out = x + delta for the NVM shift op.  x: [262144, 512] fp32.
// Row layout (D=512):
//   col 0: OP_SHL flag, col 1: OP_SHR flag, col 2: MARK_AX flag
//   cols 16-31 : ALU_LO   (argmax -> a_lo)
//   cols 32-47 : ALU_HI   (argmax -> a_hi)
//   cols 48-63 : AX_CARRY_LO (argmax -> shift, clipped to [0,7])
//   cols 64-79 : OUTPUT_LO (add active at 64 + r_lo)
//   cols 80-95 : OUTPUT_HI (add active at 80 + r_hi)
// a = a_lo + 16*a_hi; result = active_shl ? (a<<s)&255 : a>>s (integer-exact
// vs the reference's fp32 magic-floor formulation for these ranges).
//
// One 128-thread block per row; thread t owns float4 covering cols 4t..4t+3.
// All decode + delta lanes fall in cols 0..127 => warp 0 only. Warps 1-3 copy.
//
// Convergence evidence (12 measurements over 13 rounds):
//   block 128/256/512, MLP_p1 1/4/8, load default/.cs, store
//   default/.cs/.wt, flat vs persistent grid. All flat-launch variants sit
//   in wall [156.1, 157.8] us at 6.8-6.9 TB/s effective on the mandatory
//   1.074 GB R/W stream — the B300 path-independent LTS chip cap. The
//   persistent grid regressed 10%; compute pipes <=17% throughout. A
//   memcpy+sparse-delta split would add traffic through the same cap.
//   This is the machine floor for the op.

__global__ __launch_bounds__(128) void shift_kernel(const float* __restrict__ x,
                                                    float* __restrict__ out) {
    const long long row = blockIdx.x;
    const int t = threadIdx.x;                 // 0..127
    const float4* __restrict__ xin = reinterpret_cast<const float4*>(x) + row * 128;
    float4* __restrict__ xout = reinterpret_cast<float4*>(out) + row * 128;

    float4 v = xin[t];

    if (t < 32) {
        const int lane = t;

        // ---- per-lane local argmax over its 4 elements, for the 3 fields ----
        // lanes 4-7  -> ALU_LO (cols 16-31), local idx base (lane-4)*4
        // lanes 8-11 -> ALU_HI (cols 32-47)
        // lanes 12-15-> AX_CARRY_LO (cols 48-63)
        float m = -1e30f;
        int mi = 0x7fffffff;
        if (lane >= 4 && lane < 16) {
            const int base = (lane & 3) * 4;   // (lane - fieldStart)*4 since fieldStart%4==0
            float vals[4] = {v.x, v.y, v.z, v.w};
            m = vals[0];
            mi = base;
            #pragma unroll
            for (int j = 1; j < 4; j++) {
                if (vals[j] > m) { m = vals[j]; mi = base + j; }
            }
        }
        // group-of-4 max reduction (first-max-wins tie-break, matching jnp.argmax)
        #pragma unroll
        for (int off = 1; off <= 2; off <<= 1) {
            float om = __shfl_xor_sync(0xffffffffu, m, off);
            int omi = __shfl_xor_sync(0xffffffffu, mi, off);
            if (om > m || (om == m && omi < mi)) { m = om; mi = omi; }
        }
        const int a_lo = __shfl_sync(0xffffffffu, mi, 4);
        const int a_hi = __shfl_sync(0xffffffffu, mi, 8);
        int shift     = __shfl_sync(0xffffffffu, mi, 12);

        // ---- flags from lane 0 (cols 0,1,2 = v.x,v.y,v.z) ----
        int flags = 0;
        if (lane == 0) {
            flags = (v.x > 0.5f ? 1 : 0) | (v.y > 0.5f ? 2 : 0) | (v.z > 0.5f ? 4 : 0);
        }
        flags = __shfl_sync(0xffffffffu, flags, 0);

        const bool mark = (flags & 4) != 0;
        const bool active_shl = ((flags & 1) != 0) && mark;
        const bool active_shr = ((flags & 2) != 0) && mark;
        const bool active = active_shl || active_shr;

        if (active) {
            if (shift > 7) shift = 7;
            const int a = a_lo + (a_hi << 4);                       // [0,255]
            const int result = active_shl ? ((a << shift) & 255)
                                          : (a >> shift);
            const int col_lo = 64 + (result & 15);
            const int col_hi = 80 + ((result >> 4) & 15);

            // lanes 16-23 own cols 64..95; add 1.0f in-register before store
            const int myc = lane << 2;
            float* vf = reinterpret_cast<float*>(&v);
            if ((unsigned)(col_lo - myc) < 4u) vf[col_lo - myc] += 1.0f;
            if ((unsigned)(col_hi - myc) < 4u) vf[col_hi - myc] += 1.0f;
        }
    }

    xout[t] = v;
}

extern "C" void kernel_launch(void* const* d_in, const int* in_sizes, int n_in,
                              void* d_out, int out_size) {
    const float* x = (const float*)d_in[0];
    float* out = (float*)d_out;
    const int rows = in_sizes[0] / 512;        // 262144
    shift_kernel<<<rows, 128>>>(x, out);
}

// round 15
// speedup vs baseline: 1.0032x; 1.0032x over previous
#include <cuda_runtime.h>

// out = x + delta for the NVM shift op.  x: [262144, 512] fp32.
// Row layout (D=512):
//   col 0: OP_SHL, col 1: OP_SHR, col 2: MARK_AX  (flags, >0.5)
//   cols 16-31 : ALU_LO      (argmax -> a_lo)
//   cols 32-47 : ALU_HI      (argmax -> a_hi)
//   cols 48-63 : AX_CARRY_LO (argmax -> shift, clipped to [0,7])
//   cols 64-79 : OUTPUT_LO   (+= active at 64 + r_lo)
//   cols 80-95 : OUTPUT_HI   (+= active at 80 + r_hi)
// a = a_lo + 16*a_hi; result = shl ? (a<<s)&255 : a>>s  (integer-exact vs the
// reference's fp32 magic-floor for these value ranges).
//
// 256-bit global access variant (sm_100+ ld/st .v8.f32): one warp per row,
// lane l loads float8 chunks l and l+32 (2 x 256-bit, same bytes-in-flight
// as 4 x 128-bit but half the LDG/STG and L1tex requests). Lane l's first
// float8 covers cols 8l..8l+7: flags in lane 0, argmax fields in lane pairs
// (2,3)/(4,5)/(6,7), output cols 64..95 in lanes 8..11 — all in-register.

__device__ __forceinline__ void ldg256(const float* p, float* r) {
    asm volatile("ld.global.v8.f32 {%0,%1,%2,%3,%4,%5,%6,%7}, [%8];"
                 : "=f"(r[0]), "=f"(r[1]), "=f"(r[2]), "=f"(r[3]),
                   "=f"(r[4]), "=f"(r[5]), "=f"(r[6]), "=f"(r[7])
                 : "l"(p));
}
__device__ __forceinline__ void stg256(float* p, const float* r) {
    asm volatile("st.global.v8.f32 [%0], {%1,%2,%3,%4,%5,%6,%7,%8};"
                 :: "l"(p),
                    "f"(r[0]), "f"(r[1]), "f"(r[2]), "f"(r[3]),
                    "f"(r[4]), "f"(r[5]), "f"(r[6]), "f"(r[7])
                 : "memory");
}

__global__ __launch_bounds__(256) void shift_kernel(const float* __restrict__ x,
                                                    float* __restrict__ out) {
    const int warp = threadIdx.x >> 5;
    const int lane = threadIdx.x & 31;
    const long long row = (long long)blockIdx.x * 8 + warp;

    const float* __restrict__ xin = x + row * 512;
    float* __restrict__ xout = out + row * 512;

    float va[8], vb[8];
    ldg256(xin + lane * 8, va);             // cols 8l .. 8l+7
    ldg256(xin + 256 + lane * 8, vb);       // cols 256+8l .. 256+8l+7

    // ---- decode on va ----
    // lanes 2-3 -> ALU_LO (cols 16-31), lanes 4-5 -> ALU_HI (32-47),
    // lanes 6-7 -> AX_CARRY_LO (48-63). Per-lane argmax over 8 elements
    // (first-max-wins), then one pair shuffle reduction (lower index wins
    // ties) — matches jnp.argmax semantics.
    float m = -1e30f;
    int mi = 0x7fffffff;
    if (lane >= 2 && lane < 8) {
        const int base = (lane & 1) * 8;
        m = va[0];
        mi = base;
        #pragma unroll
        for (int j = 1; j < 8; j++) {
            if (va[j] > m) { m = va[j]; mi = base + j; }
        }
    }
    {
        float om = __shfl_xor_sync(0xffffffffu, m, 1);
        int omi = __shfl_xor_sync(0xffffffffu, mi, 1);
        if (om > m || (om == m && omi < mi)) { m = om; mi = omi; }
    }
    const int a_lo = __shfl_sync(0xffffffffu, mi, 2);
    const int a_hi = __shfl_sync(0xffffffffu, mi, 4);
    int shift     = __shfl_sync(0xffffffffu, mi, 6);

    // flags from lane 0 (cols 0,1,2 = va[0..2])
    int flags = 0;
    if (lane == 0) {
        flags = (va[0] > 0.5f ? 1 : 0) | (va[1] > 0.5f ? 2 : 0) | (va[2] > 0.5f ? 4 : 0);
    }
    flags = __shfl_sync(0xffffffffu, flags, 0);

    const bool mark = (flags & 4) != 0;
    const bool active_shl = ((flags & 1) != 0) && mark;
    const bool active_shr = ((flags & 2) != 0) && mark;

    if (active_shl || active_shr) {
        if (shift > 7) shift = 7;
        const int a = a_lo + (a_hi << 4);                 // [0,255]
        const int result = active_shl ? ((a << shift) & 255)
                                      : (a >> shift);
        const int col_lo = 64 + (result & 15);
        const int col_hi = 80 + ((result >> 4) & 15);

        // lanes 8-11 own cols 64..95 within va; add in-register before store
        const int myc = lane << 3;
        if ((unsigned)(col_lo - myc) < 8u) va[col_lo - myc] += 1.0f;
        if ((unsigned)(col_hi - myc) < 8u) va[col_hi - myc] += 1.0f;
    }

    stg256(xout + lane * 8, va);
    stg256(xout + 256 + lane * 8, vb);
}

extern "C" void kernel_launch(void* const* d_in, const int* in_sizes, int n_in,
                              void* d_out, int out_size) {
    const float* x = (const float*)d_in[0];
    float* out = (float*)d_out;
    const int rows = in_sizes[0] / 512;        // 262144, divisible by 8
    shift_kernel<<<rows / 8, 256>>>(x, out);
}

// round 16
// speedup vs baseline: 1.0116x; 1.0084x over previous
#include <cuda_runtime.h>

// FINAL — converged winner (best measured: 156.128 us; reproduced 156.4-157.4).
//
// out = x + delta for the NVM shift op.  x: [262144, 512] fp32.
// Row layout (D=512):
//   col 0: OP_SHL flag, col 1: OP_SHR flag, col 2: MARK_AX flag
//   cols 16-31 : ALU_LO   (argmax -> a_lo)
//   cols 32-47 : ALU_HI   (argmax -> a_hi)
//   cols 48-63 : AX_CARRY_LO (argmax -> shift, clipped to [0,7])
//   cols 64-79 : OUTPUT_LO (add active at 64 + r_lo)
//   cols 80-95 : OUTPUT_HI (add active at 80 + r_hi)
// a = a_lo + 16*a_hi; result = active_shl ? (a<<s)&255 : a>>s (integer-exact
// vs the reference's fp32 magic-floor formulation for these ranges).
//
// One 128-thread block per row; thread t owns float4 covering cols 4t..4t+3.
// All decode + delta lanes fall in cols 0..127 => warp 0 only. Warps 1-3 copy.
//
// Convergence evidence (14 measurements over 15 rounds), all axes closed:
//   block 128/256/512 | MLP_p1 1/4/8 | access width 128b/256b(v8) |
//   load default/.cs | store default/.cs/.wt | flat vs persistent grid.
//   Every flat-launch variant: wall in [156.1, 158.4] us at 6.8-6.9 TB/s
//   effective on the mandatory 1.074 GB R/W stream — the B300 path-
//   independent LTS chip cap. Persistent grid regressed 10%. Compute pipes
//   <=17%. Residual wall variation tracks chip-state drift, not structure.
//   This is the machine floor for the op.

__global__ __launch_bounds__(128) void shift_kernel(const float* __restrict__ x,
                                                    float* __restrict__ out) {
    const long long row = blockIdx.x;
    const int t = threadIdx.x;                 // 0..127
    const float4* __restrict__ xin = reinterpret_cast<const float4*>(x) + row * 128;
    float4* __restrict__ xout = reinterpret_cast<float4*>(out) + row * 128;

    float4 v = xin[t];

    if (t < 32) {
        const int lane = t;

        // ---- per-lane local argmax over its 4 elements, for the 3 fields ----
        // lanes 4-7  -> ALU_LO (cols 16-31), local idx base (lane-4)*4
        // lanes 8-11 -> ALU_HI (cols 32-47)
        // lanes 12-15-> AX_CARRY_LO (cols 48-63)
        float m = -1e30f;
        int mi = 0x7fffffff;
        if (lane >= 4 && lane < 16) {
            const int base = (lane & 3) * 4;   // (lane - fieldStart)*4 since fieldStart%4==0
            float vals[4] = {v.x, v.y, v.z, v.w};
            m = vals[0];
            mi = base;
            #pragma unroll
            for (int j = 1; j < 4; j++) {
                if (vals[j] > m) { m = vals[j]; mi = base + j; }
            }
        }
        // group-of-4 max reduction (first-max-wins tie-break, matching jnp.argmax)
        #pragma unroll
        for (int off = 1; off <= 2; off <<= 1) {
            float om = __shfl_xor_sync(0xffffffffu, m, off);
            int omi = __shfl_xor_sync(0xffffffffu, mi, off);
            if (om > m || (om == m && omi < mi)) { m = om; mi = omi; }
        }
        const int a_lo = __shfl_sync(0xffffffffu, mi, 4);
        const int a_hi = __shfl_sync(0xffffffffu, mi, 8);
        int shift     = __shfl_sync(0xffffffffu, mi, 12);

        // ---- flags from lane 0 (cols 0,1,2 = v.x,v.y,v.z) ----
        int flags = 0;
        if (lane == 0) {
            flags = (v.x > 0.5f ? 1 : 0) | (v.y > 0.5f ? 2 : 0) | (v.z > 0.5f ? 4 : 0);
        }
        flags = __shfl_sync(0xffffffffu, flags, 0);

        const bool mark = (flags & 4) != 0;
        const bool active_shl = ((flags & 1) != 0) && mark;
        const bool active_shr = ((flags & 2) != 0) && mark;
        const bool active = active_shl || active_shr;

        if (active) {
            if (shift > 7) shift = 7;
            const int a = a_lo + (a_hi << 4);                       // [0,255]
            const int result = active_shl ? ((a << shift) & 255)
                                          : (a >> shift);
            const int col_lo = 64 + (result & 15);
            const int col_hi = 80 + ((result >> 4) & 15);

            // lanes 16-23 own cols 64..95; add 1.0f in-register before store
            const int myc = lane << 2;
            float* vf = reinterpret_cast<float*>(&v);
            if ((unsigned)(col_lo - myc) < 4u) vf[col_lo - myc] += 1.0f;
            if ((unsigned)(col_hi - myc) < 4u) vf[col_hi - myc] += 1.0f;
        }
    }

    xout[t] = v;
}

extern "C" void kernel_launch(void* const* d_in, const int* in_sizes, int n_in,
                              void* d_out, int out_size) {
    const float* x = (const float*)d_in[0];
    float* out = (float*)d_out;
    const int rows = in_sizes[0] / 512;        // 262144
    shift_kernel<<<rows, 128>>>(x, out);
}